// round 6
// baseline (speedup 1.0000x reference)
#include <cuda_runtime.h>
#include <math.h>

#define NPTS   8192
#define BATCH  2
#define TI     128                 // rows per block tile
#define TJ     512                 // cols per block tile
#define IT     (NPTS / TI)         // 64 row tiles
#define JT     (NPTS / TJ)         // 16 col tiles
#define THREADS 256
#define RP     4                   // row-pairs per thread (8 rows), ty: 16 groups
#define JPT    (TJ / 16)           // 32 cols per thread, tx: 16 lanes
#define CRP    (TJ + 8)            // colred row pitch

// Partials: each written by exactly one block (no atomics, deterministic).
__device__ float g_rowpart[JT][BATCH * NPTS];
__device__ float g_colpart[IT][BATCH * NPTS];
__device__ float g_bsum[128];

// ---- packed f32x2 helpers --------------------------------------------------
static __device__ __forceinline__ unsigned long long pack2(float lo, float hi) {
    unsigned long long r;
    asm("mov.b64 %0, {%1, %2};" : "=l"(r) : "f"(lo), "f"(hi));
    return r;
}
static __device__ __forceinline__ void unpack2(unsigned long long v, float& lo, float& hi) {
    asm("mov.b64 {%0, %1}, %2;" : "=f"(lo), "=f"(hi) : "l"(v));
}
static __device__ __forceinline__ unsigned long long fma2(
    unsigned long long a, unsigned long long b, unsigned long long c) {
    unsigned long long d;
    asm("fma.rn.f32x2 %0, %1, %2, %3;" : "=l"(d) : "l"(a), "l"(b), "l"(c));
    return d;
}
static __device__ __forceinline__ unsigned long long add2(
    unsigned long long a, unsigned long long b) {
    unsigned long long d;
    asm("add.rn.f32x2 %0, %1, %2;" : "=l"(d) : "l"(a), "l"(b));
    return d;
}

// Grid (IT, JT, BATCH). Tile: 128 gt-rows x 512 pred-cols.
// f32x2 lanes hold TWO ROWS of the same column: query packs need no duplication
// (32 regs), the column values are duplicated in smem instead.
__global__ void __launch_bounds__(THREADS, 4)
fused_kernel(const float* __restrict__ pred, const float* __restrict__ gt) {
    __shared__ float4 qrow[TI];        // (x, y, z, g2)                2 KB
    __shared__ float4 dupA[TJ];        // {-2x,-2x,-2y,-2y} per col    8 KB
    __shared__ float4 dupB[TJ];        // {-2z,-2z, p2, p2} per col    8 KB
    __shared__ float  colred[8][CRP];  // per-warp col mins          ~16.3 KB

    int it = blockIdx.x, jt = blockIdx.y, b = blockIdx.z;
    int tid = threadIdx.x;

    for (int i = tid; i < TI; i += THREADS) {
        const float* g = gt + (long)(b * NPTS + it * TI + i) * 3;
        float x = g[0], y = g[1], z = g[2];
        qrow[i] = make_float4(x, y, z, x * x + y * y + z * z);
    }
    for (int p = tid; p < TJ; p += THREADS) {
        const float* q = pred + (long)(b * NPTS + jt * TJ + p) * 3;
        float x = q[0], y = q[1], z = q[2];
        dupA[p] = make_float4(-2.f * x, -2.f * x, -2.f * y, -2.f * y);
        float p2 = x * x + y * y + z * z;
        dupB[p] = make_float4(-2.f * z, -2.f * z, p2, p2);
    }
    __syncthreads();

    int ty = tid >> 4, tx = tid & 15;

    unsigned long long qx2[RP], qy2[RP], qz2[RP], g22[RP];
    float rowacc[2 * RP];
#pragma unroll
    for (int rp = 0; rp < RP; rp++) {
        float4 a = qrow[ty * 8 + 2 * rp];
        float4 c = qrow[ty * 8 + 2 * rp + 1];
        qx2[rp] = pack2(a.x, c.x);
        qy2[rp] = pack2(a.y, c.y);
        qz2[rp] = pack2(a.z, c.z);
        g22[rp] = pack2(a.w, c.w);
        rowacc[2 * rp] = 3.4e38f; rowacc[2 * rp + 1] = 3.4e38f;
    }

    const ulonglong2* cA = (const ulonglong2*)dupA;
    const ulonglong2* cB = (const ulonglong2*)dupB;
#pragma unroll 4
    for (int jp = 0; jp < JPT; jp++) {
        int c = jp * 16 + tx;               // lanes: consecutive 16B chunks
        ulonglong2 A  = cA[c];              // {(-2x,-2x), (-2y,-2y)}
        ulonglong2 Bv = cB[c];              // {(-2z,-2z), ( p2, p2)}
        float cacc = 3.4e38f;
#pragma unroll
        for (int rp = 0; rp < RP; rp++) {
            // s = (p2 - 2<g,p>) + g2, two rows at once
            unsigned long long t =
                fma2(qx2[rp], A.x, fma2(qy2[rp], A.y, fma2(qz2[rp], Bv.x, Bv.y)));
            unsigned long long s = add2(t, g22[rp]);
            float slo, shi; unpack2(s, slo, shi);
            rowacc[2 * rp]     = fminf(rowacc[2 * rp], slo);
            rowacc[2 * rp + 1] = fminf(rowacc[2 * rp + 1], shi);
            cacc = fminf(cacc, fminf(slo, shi));   // tree: short cacc chain
        }
        // warp-partner (xor 16) owns the same column with the other ty group
        float co = __shfl_xor_sync(0xffffffffu, cacc, 16);
        cacc = fminf(cacc, co);
        if ((tid & 31) < 16)
            colred[tid >> 5][c] = cacc;
    }

    // Row mins: butterfly over the 16 tx lanes (masks stay inside halves).
#pragma unroll
    for (int k = 0; k < 2 * RP; k++) {
        float v = rowacc[k];
        v = fminf(v, __shfl_xor_sync(0xffffffffu, v, 1));
        v = fminf(v, __shfl_xor_sync(0xffffffffu, v, 2));
        v = fminf(v, __shfl_xor_sync(0xffffffffu, v, 4));
        v = fminf(v, __shfl_xor_sync(0xffffffffu, v, 8));
        if (tx == 0)
            g_rowpart[jt][(b << 13) + it * TI + ty * 8 + k] = v;
    }

    __syncthreads();
    // Col mins over the 8 warp slices; index s0 IS the tile column.
    for (int s0 = tid; s0 < TJ; s0 += THREADS) {
        float m = colred[0][s0];
#pragma unroll
        for (int w = 1; w < 8; w++) m = fminf(m, colred[w][s0]);
        g_colpart[it][(b << 13) + jt * TJ + s0] = m;
    }
}

// 128 blocks x 128 threads = 16384 items; one gt-row min + one pred-col min each.
__global__ void __launch_bounds__(128)
reduce2_kernel() {
    int idx = blockIdx.x * 128 + threadIdx.x;
    float rm = g_rowpart[0][idx];
#pragma unroll
    for (int j = 1; j < JT; j++) rm = fminf(rm, g_rowpart[j][idx]);
    float cm = g_colpart[0][idx];
#pragma unroll
    for (int i = 1; i < IT; i++) cm = fminf(cm, g_colpart[i][idx]);
    float s = sqrtf(fmaxf(rm, 0.f)) + sqrtf(fmaxf(cm, 0.f));

    __shared__ float sb[128];
    sb[threadIdx.x] = s;
    __syncthreads();
    for (int off = 64; off > 0; off >>= 1) {
        if (threadIdx.x < off) sb[threadIdx.x] += sb[threadIdx.x + off];
        __syncthreads();
    }
    if (threadIdx.x == 0) g_bsum[blockIdx.x] = sb[0];
}

__global__ void __launch_bounds__(128)
reduce3_kernel(float* __restrict__ out) {
    __shared__ float sb[128];
    sb[threadIdx.x] = g_bsum[threadIdx.x];
    __syncthreads();
    for (int off = 64; off > 0; off >>= 1) {
        if (threadIdx.x < off) sb[threadIdx.x] += sb[threadIdx.x + off];
        __syncthreads();
    }
    if (threadIdx.x == 0) out[0] = sb[0] / (float)(BATCH * NPTS);
}

extern "C" void kernel_launch(void* const* d_in, const int* in_sizes, int n_in,
                              void* d_out, int out_size) {
    const float* pred = (const float*)d_in[0];
    const float* gt   = (const float*)d_in[1];
    float* out = (float*)d_out;

    dim3 grid(IT, JT, BATCH);
    fused_kernel<<<grid, THREADS>>>(pred, gt);
    reduce2_kernel<<<128, 128>>>();
    reduce3_kernel<<<1, 128>>>(out);
}